// round 6
// baseline (speedup 1.0000x reference)
#include <cuda_runtime.h>
#include <math.h>
#include <stdint.h>

#define TT 128
#define NN 1000
#define EE 16000
#define FF 397
#define HH 128
#define DD 8
#define G4 512   // 4*HH
#define BM 128
#define BK 16

// ---- static scratch (allocation-free rule: __device__ globals) ----
__device__ float g_Y [TT*NN*HH];
__device__ float g_H1[TT*NN*HH];
__device__ int   g_cnt  [TT*NN];
__device__ int   g_start[TT*NN];
__device__ int   g_eidx [TT*EE];
__device__ float g_pool [TT*HH];
__device__ float g_Gx   [TT*G4];

// ---- packed f32x2 helpers ----
__device__ __forceinline__ unsigned long long pack2(float x, float y) {
    unsigned long long r;
    asm("mov.b64 %0, {%1, %2};" : "=l"(r) : "f"(x), "f"(y));
    return r;
}
__device__ __forceinline__ void ffma2(unsigned long long& d,
                                      unsigned long long a, unsigned long long b) {
    asm("fma.rn.f32x2 %0, %1, %2, %3;" : "=l"(d) : "l"(a), "l"(b), "l"(d));
}
__device__ __forceinline__ float2 unpack2(unsigned long long v) {
    float2 r;
    asm("mov.b64 {%0, %1}, %2;" : "=f"(r.x), "=f"(r.y) : "l"(v));
    return r;
}
__device__ __forceinline__ uint32_t smem_u32(const void* p) {
    uint32_t a;
    asm("{ .reg .u64 t; cvta.to.shared.u64 t, %1; cvt.u32.u64 %0, t; }" : "=r"(a) : "l"(p));
    return a;
}
// 4B async copy with zero-fill predicate (src-size 0 reads nothing)
__device__ __forceinline__ void cpa4(uint32_t dst, const float* src, bool pred) {
    asm volatile("cp.async.ca.shared.global [%0], [%1], 4, %2;"
                 :: "r"(dst), "l"(src), "r"(pred ? 4u : 0u) : "memory");
}

// ---------------- fused CSR build: one block per timestep ----------------
__global__ void __launch_bounds__(1024) csr_kernel(const int* __restrict__ ei) {
    __shared__ int scnt[1024];
    __shared__ int sscan[1024];
    int t = blockIdx.x, tid = threadIdx.x;
    scnt[tid] = 0;
    __syncthreads();
    const int* srcp = ei + t*2*EE;
    const int* dstp = srcp + EE;
    for (int e = tid; e < EE; e += 1024) atomicAdd(&scnt[dstp[e]], 1);
    __syncthreads();
    int v = scnt[tid];
    sscan[tid] = v;
    __syncthreads();
    for (int off = 1; off < 1024; off <<= 1) {
        int u = (tid >= off) ? sscan[tid - off] : 0;
        __syncthreads();
        sscan[tid] += u;
        __syncthreads();
    }
    int start = sscan[tid] - v;
    if (tid < NN) { g_start[t*NN + tid] = start; g_cnt[t*NN + tid] = v; }
    __syncthreads();
    scnt[tid] = start;          // reuse as cursor
    __syncthreads();
    int* eix = g_eidx + t*EE;
    for (int e = tid; e < EE; e += 1024) {
        int d = dstp[e], s = srcp[e];
        int pos = atomicAdd(&scnt[d], 1);
        eix[pos] = s;
    }
}

// ------- GEMM: C[M x 128] = A[M x K] @ W^T + bias --------
// FFMA2 mainloop (R5) + cp.async double-buffered tiles (R6).
// BM=128, BN=128, BK=16, 256 threads, 2 CTAs/SM. Per-thread 8m x 8n.
// B smem: u64 slot j of row k = (W[j][k], W[j+64][k]); thread tx reads
// slots {tx,tx+16,tx+32,tx+48}: 8B lane stride, conflict-free.
__global__ void __launch_bounds__(256, 2) gemm_bias_kernel(
    const float* __restrict__ A, const float* __restrict__ W,
    const float* __restrict__ bias, float* __restrict__ C, int K)
{
    __shared__ float As [2][BK][BM];      // 2 x 8 KB
    __shared__ float Bsf[2][BK][2*64];    // 2 x 8 KB
    int tid = threadIdx.x;
    long m0 = (long)blockIdx.x * BM;

    int tx = tid & 15, ty = tid >> 4;
    int tm = ty * 8;

    unsigned long long acc[8][4];
    #pragma unroll
    for (int i = 0; i < 8; i++)
        #pragma unroll
        for (int j = 0; j < 4; j++) acc[i][j] = 0ULL;

    int ar = tid >> 1, ak = (tid & 1) * 8;
    const float* Arow = A + (m0 + ar) * (long)K;
    int wn = tid >> 1, wk = (tid & 1) * 8;
    const float* Wrow = W + (long)wn * K;
    int wslot = 2*(wn & 63) + (wn >> 6);

    uint32_t sA = smem_u32(&As[0][0][0]);
    uint32_t sB = smem_u32(&Bsf[0][0][0]);

    int NT = (K + BK - 1) / BK;

    // issue one tile's async copies (16 x 4B per thread)
    auto issue_tile = [&](int it, int buf) {
        int k0 = it * BK;
        uint32_t ab = sA + (uint32_t)(buf*BK*BM)*4u;
        uint32_t bb = sB + (uint32_t)(buf*BK*128)*4u;
        #pragma unroll
        for (int i = 0; i < 8; i++) {
            int k = k0 + ak + i;
            cpa4(ab + (uint32_t)((ak + i)*BM + ar)*4u, Arow + k, k < K);
        }
        #pragma unroll
        for (int i = 0; i < 8; i++) {
            int k = k0 + wk + i;
            cpa4(bb + (uint32_t)((wk + i)*128 + wslot)*4u, Wrow + k, k < K);
        }
        asm volatile("cp.async.commit_group;" ::: "memory");
    };

    issue_tile(0, 0);
    for (int it = 0; it < NT; it++) {
        int buf = it & 1;
        if (it + 1 < NT) {
            issue_tile(it + 1, buf ^ 1);
            asm volatile("cp.async.wait_group 1;" ::: "memory");
        } else {
            asm volatile("cp.async.wait_group 0;" ::: "memory");
        }
        __syncthreads();
        #pragma unroll
        for (int k = 0; k < BK; k++) {
            float4 a0 = *(const float4*)&As[buf][k][tm];
            float4 a1 = *(const float4*)&As[buf][k][tm + 4];
            const unsigned long long* bp = (const unsigned long long*)&Bsf[buf][k][0];
            unsigned long long b[4];
            b[0] = bp[tx]; b[1] = bp[tx + 16]; b[2] = bp[tx + 32]; b[3] = bp[tx + 48];
            unsigned long long ad[8];
            ad[0] = pack2(a0.x, a0.x); ad[1] = pack2(a0.y, a0.y);
            ad[2] = pack2(a0.z, a0.z); ad[3] = pack2(a0.w, a0.w);
            ad[4] = pack2(a1.x, a1.x); ad[5] = pack2(a1.y, a1.y);
            ad[6] = pack2(a1.z, a1.z); ad[7] = pack2(a1.w, a1.w);
            #pragma unroll
            for (int i = 0; i < 8; i++)
                #pragma unroll
                for (int j = 0; j < 4; j++)
                    ffma2(acc[i][j], ad[i], b[j]);
        }
        __syncthreads();
    }

    // epilogue: thread writes cols {tx+16r} and {tx+16r+64}, rows tm..tm+7
    float blo[4], bhi[4];
    #pragma unroll
    for (int j = 0; j < 4; j++) {
        blo[j] = bias[tx + 16*j];
        bhi[j] = bias[tx + 16*j + 64];
    }
    #pragma unroll
    for (int i = 0; i < 8; i++) {
        float* crow = C + (m0 + tm + i) * (long)HH;
        #pragma unroll
        for (int j = 0; j < 4; j++) {
            float2 v = unpack2(acc[i][j]);
            crow[tx + 16*j]      = v.x + blo[j];
            crow[tx + 16*j + 64] = v.y + bhi[j];
        }
    }
}

// -------- gather + relu (GIN self-term + neighbor sum + ReLU) --------
__global__ void __launch_bounds__(256) gather_relu_kernel(
    const float* __restrict__ Y, float* __restrict__ Out)
{
    int wid  = threadIdx.x >> 5, lane = threadIdx.x & 31;
    int dst  = blockIdx.x * 8 + wid;
    int t    = blockIdx.y;
    if (dst >= NN) return;
    const float* base = Y + t * NN * HH;
    float4 acc = *(const float4*)&base[dst * HH + lane * 4];
    int s   = g_start[t*NN + dst];
    int cnt = g_cnt  [t*NN + dst];
    const int* ep = g_eidx + t*EE + s;
    int i = 0;
    for (; i + 4 <= cnt; i += 4) {
        int s0 = ep[i], s1 = ep[i+1], s2 = ep[i+2], s3 = ep[i+3];
        float4 v0 = *(const float4*)&base[s0*HH + lane*4];
        float4 v1 = *(const float4*)&base[s1*HH + lane*4];
        float4 v2 = *(const float4*)&base[s2*HH + lane*4];
        float4 v3 = *(const float4*)&base[s3*HH + lane*4];
        acc.x += v0.x + v1.x + v2.x + v3.x;
        acc.y += v0.y + v1.y + v2.y + v3.y;
        acc.z += v0.z + v1.z + v2.z + v3.z;
        acc.w += v0.w + v1.w + v2.w + v3.w;
    }
    for (; i < cnt; i++) {
        int s0 = ep[i];
        float4 v = *(const float4*)&base[s0*HH + lane*4];
        acc.x += v.x; acc.y += v.y; acc.z += v.z; acc.w += v.w;
    }
    acc.x = fmaxf(acc.x, 0.f); acc.y = fmaxf(acc.y, 0.f);
    acc.z = fmaxf(acc.z, 0.f); acc.w = fmaxf(acc.w, 0.f);
    *(float4*)&Out[(t*NN + dst)*HH + lane*4] = acc;
}

// ---------------- mean pool over N ----------------
__global__ void pool_kernel(const float* __restrict__ Hin) {
    int t = blockIdx.x, c = threadIdx.x;   // 128 threads
    const float* p = Hin + t*NN*HH + c;
    float s0 = 0, s1 = 0, s2 = 0, s3 = 0;
    for (int n = 0; n < NN; n += 4) {
        s0 += p[(n+0)*HH];
        s1 += p[(n+1)*HH];
        s2 += p[(n+2)*HH];
        s3 += p[(n+3)*HH];
    }
    g_pool[t*HH + c] = (s0 + s1 + s2 + s3) * (1.f / NN);
}

// -------- input-side LSTM gates --------
__global__ void __launch_bounds__(512) gx_kernel(
    const int* __restrict__ dok, const float* __restrict__ emb,
    const float* __restrict__ w_ih, const float* __restrict__ b_ih,
    const float* __restrict__ b_hh)
{
    __shared__ float sseq[HH + DD];
    int t = blockIdx.x, j = threadIdx.x;
    if (j < HH)            sseq[j] = g_pool[t*HH + j];
    else if (j < HH + DD)  sseq[j] = emb[dok[t]*DD + (j - HH)];
    __syncthreads();
    const float* wr = w_ih + j * (HH + DD);
    float a0 = b_ih[j] + b_hh[j], a1 = 0.f;
    #pragma unroll
    for (int k = 0; k < HH + DD; k += 2) {
        a0 += wr[k]   * sseq[k];
        a1 += wr[k+1] * sseq[k+1];
    }
    g_Gx[t*G4 + j] = a0 + a1;
}

// ---------------- sequential LSTM + final FC ----------------
#define SPITCH 68
__global__ void __launch_bounds__(512) lstm_kernel(
    const float* __restrict__ w_hh, const float* __restrict__ w_fc,
    const float* __restrict__ b_fc, float* __restrict__ out)
{
    extern __shared__ float sm[];
    float* sW   = sm;                  // 512*68
    float* sh   = sW + G4*SPITCH;      // 128
    float* sg   = sh + HH;             // 512
    float* sred = sg + G4;             // 32

    int tid = threadIdx.x;

    float4 rw[16];
    const float4* wg4 = (const float4*)(w_hh + tid * HH);
    #pragma unroll
    for (int i = 0; i < 16; i++) rw[i] = wg4[i];          // cols 0..63

    for (int i = tid; i < G4 * 64; i += 512) {            // cols 64..127
        int r = i >> 6, c = i & 63;
        sW[r*SPITCH + c] = w_hh[r*HH + 64 + c];
    }
    if (tid < HH) sh[tid] = 0.f;
    float c_state = 0.f;
    float wfc = (tid < HH) ? w_fc[tid] : 0.f;
    float bfc = b_fc[0];
    __syncthreads();

    const float4* wr4 = (const float4*)(sW + tid * SPITCH);

    for (int t = 0; t < TT; t++) {
        const float4* sh4 = (const float4*)sh;
        float a0 = 0, a1 = 0, a2 = 0, a3 = 0;
        #pragma unroll
        for (int k = 0; k < 16; k++) {
            float4 hv = sh4[k]; float4 w = rw[k];
            a0 += w.x*hv.x; a1 += w.y*hv.y; a2 += w.z*hv.z; a3 += w.w*hv.w;
        }
        #pragma unroll
        for (int k = 0; k < 16; k++) {
            float4 hv = sh4[16 + k]; float4 w = wr4[k];
            a0 += w.x*hv.x; a1 += w.y*hv.y; a2 += w.z*hv.z; a3 += w.w*hv.w;
        }
        sg[tid] = g_Gx[t*G4 + tid] + (a0 + a1) + (a2 + a3);
        __syncthreads();
        if (tid < HH) {
            float ig = 1.f / (1.f + expf(-sg[tid]));
            float fg = 1.f / (1.f + expf(-sg[tid + HH]));
            float gg = tanhf(sg[tid + 2*HH]);
            float og = 1.f / (1.f + expf(-sg[tid + 3*HH]));
            c_state = fg * c_state + ig * gg;
            float h = og * tanhf(c_state);
            sh[tid] = h;
            float p = h * wfc;
            #pragma unroll
            for (int o = 16; o > 0; o >>= 1) p += __shfl_down_sync(0xffffffffu, p, o);
            if ((tid & 31) == 0) sred[tid >> 5] = p;
        }
        __syncthreads();
        if (tid == 0) out[t] = sred[0] + sred[1] + sred[2] + sred[3] + bfc;
    }
}

// ---------------- launch ----------------
extern "C" void kernel_launch(void* const* d_in, const int* in_sizes, int n_in,
                              void* d_out, int out_size)
{
    const float* x    = (const float*)d_in[0];
    const int*   ei   = (const int*)  d_in[1];
    const int*   dok  = (const int*)  d_in[2];
    const float* w1   = (const float*)d_in[3];
    const float* b1   = (const float*)d_in[4];
    const float* w2   = (const float*)d_in[5];
    const float* b2   = (const float*)d_in[6];
    const float* emb  = (const float*)d_in[7];
    const float* w_ih = (const float*)d_in[8];
    const float* w_hh = (const float*)d_in[9];
    const float* b_ih = (const float*)d_in[10];
    const float* b_hh = (const float*)d_in[11];
    const float* w_fc = (const float*)d_in[12];
    const float* b_fc = (const float*)d_in[13];
    float* out = (float*)d_out;

    float *pY, *pH1;
    cudaGetSymbolAddress((void**)&pY,  g_Y);
    cudaGetSymbolAddress((void**)&pH1, g_H1);

    // fused CSR build (shared by both GIN layers)
    csr_kernel<<<TT, 1024>>>(ei);

    // GIN layer 1: y = x@w1^T + b1 ; h1 = relu(y[dst] + sum y[src])
    gemm_bias_kernel<<<TT*NN/BM, 256>>>(x, w1, b1, pY, FF);
    dim3 gg((NN + 7)/8, TT);
    gather_relu_kernel<<<gg, 256>>>(pY, pH1);

    // GIN layer 2
    gemm_bias_kernel<<<TT*NN/BM, 256>>>(pH1, w2, b2, pY, HH);
    gather_relu_kernel<<<gg, 256>>>(pY, pH1);

    // pool, LSTM input gates, sequential LSTM + FC
    pool_kernel<<<TT, HH>>>(pH1);
    gx_kernel<<<TT, 512>>>(dok, emb, w_ih, b_ih, b_hh);

    size_t lsm = (size_t)(G4*SPITCH + HH + G4 + 32) * sizeof(float);
    cudaFuncSetAttribute(lstm_kernel, cudaFuncAttributeMaxDynamicSharedMemorySize, (int)lsm);
    lstm_kernel<<<1, 512, lsm>>>(w_hh, w_fc, b_fc, out);
}

// round 7
// speedup vs baseline: 1.0664x; 1.0664x over previous
#include <cuda_runtime.h>
#include <math.h>
#include <stdint.h>

#define TT 128
#define NN 1000
#define EE 16000
#define FF 397
#define HH 128
#define DD 8
#define G4 512   // 4*HH
#define BM 128
#define BKT 32   // K per tile (tensor gemm)
#define PITCH 36 // smem row pitch (floats): bank = (4m+k)%32, conflict-free
#define SZF (128*PITCH)      // floats per tile buffer (A or B)
#define STAGEF (2*SZF)       // floats per stage (A+B)

// ---- static scratch (allocation-free rule: __device__ globals) ----
__device__ float g_Y [TT*NN*HH];
__device__ float g_H1[TT*NN*HH];
__device__ int   g_cnt  [TT*NN];
__device__ int   g_start[TT*NN];
__device__ int   g_eidx [TT*EE];
__device__ float g_pool [TT*HH];
__device__ float g_Gx   [TT*G4];

// ---- helpers ----
__device__ __forceinline__ uint32_t smem_u32(const void* p) {
    uint32_t a;
    asm("{ .reg .u64 t; cvta.to.shared.u64 t, %1; cvt.u32.u64 %0, t; }" : "=r"(a) : "l"(p));
    return a;
}
// 4B async copy with zero-fill predicate (src-size 0 -> writes zeros)
__device__ __forceinline__ void cpa4(uint32_t dst, const float* src, bool pred) {
    asm volatile("cp.async.ca.shared.global [%0], [%1], 4, %2;"
                 :: "r"(dst), "l"(src), "r"(pred ? 4u : 0u) : "memory");
}
__device__ __forceinline__ uint32_t cvt_tf32(float x) {
    uint32_t u; asm("cvt.rna.tf32.f32 %0, %1;" : "=r"(u) : "f"(x)); return u;
}
// legacy per-warp tensor mma: D(4xf32) += A(4xtf32) * B(2xtf32)
__device__ __forceinline__ void mma_tf32(float* d, const uint32_t* a, const uint32_t* b) {
    asm volatile("mma.sync.aligned.m16n8k8.row.col.f32.tf32.tf32.f32 "
                 "{%0,%1,%2,%3}, {%4,%5,%6,%7}, {%8,%9}, {%0,%1,%2,%3};"
                 : "+f"(d[0]), "+f"(d[1]), "+f"(d[2]), "+f"(d[3])
                 : "r"(a[0]), "r"(a[1]), "r"(a[2]), "r"(a[3]),
                   "r"(b[0]), "r"(b[1]));
}

// ---------------- fused CSR build: one block per timestep ----------------
__global__ void __launch_bounds__(1024) csr_kernel(const int* __restrict__ ei) {
    __shared__ int scnt[1024];
    __shared__ int sscan[1024];
    int t = blockIdx.x, tid = threadIdx.x;
    scnt[tid] = 0;
    __syncthreads();
    const int* srcp = ei + t*2*EE;
    const int* dstp = srcp + EE;
    for (int e = tid; e < EE; e += 1024) atomicAdd(&scnt[dstp[e]], 1);
    __syncthreads();
    int v = scnt[tid];
    sscan[tid] = v;
    __syncthreads();
    for (int off = 1; off < 1024; off <<= 1) {
        int u = (tid >= off) ? sscan[tid - off] : 0;
        __syncthreads();
        sscan[tid] += u;
        __syncthreads();
    }
    int start = sscan[tid] - v;
    if (tid < NN) { g_start[t*NN + tid] = start; g_cnt[t*NN + tid] = v; }
    __syncthreads();
    scnt[tid] = start;          // reuse as cursor
    __syncthreads();
    int* eix = g_eidx + t*EE;
    for (int e = tid; e < EE; e += 1024) {
        int d = dstp[e], s = srcp[e];
        int pos = atomicAdd(&scnt[d], 1);
        eix[pos] = s;
    }
}

// ==== tensor GEMM: C[M x 128] = A[M x K] @ W^T + bias (3xTF32 mma.sync) ====
// 512 thr = 16 warps in 4m x 4n grid; warp tile 32x32; BK=32 (4 k8 steps).
// Smem raw fp32, m-major pitch 36 (conflict-free frag loads); hi/lo tf32
// split in registers. cp.async double-buffered.
__global__ void __launch_bounds__(512, 1) gemm_mma_kernel(
    const float* __restrict__ A, const float* __restrict__ W,
    const float* __restrict__ bias, float* __restrict__ C, int K)
{
    extern __shared__ float smf[];
    int tid = threadIdx.x;
    int lane = tid & 31, wid = tid >> 5;
    long m0 = (long)blockIdx.x * BM;

    int mw = (wid & 3) * 32;      // warp m offset
    int nw = (wid >> 2) * 32;     // warp n offset

    float acc[2][4][4];
    #pragma unroll
    for (int f = 0; f < 2; f++)
        #pragma unroll
        for (int g = 0; g < 4; g++)
            #pragma unroll
            for (int e = 0; e < 4; e++) acc[f][g][e] = 0.f;

    // staging assignment: thread copies 8 consecutive k of one row
    int srow = tid >> 2, skq = (tid & 3) * 8;
    const float* Arow = A + (m0 + srow) * (long)K + skq;
    const float* Wrow = W + (long)srow * K + skq;
    uint32_t sb = smem_u32(smf);

    int NT = (K + BKT - 1) / BKT;

    auto issue_tile = [&](int it, int buf) {
        int k0 = it * BKT;
        uint32_t ab = sb + (uint32_t)(buf*STAGEF)*4u;
        uint32_t bbase = ab + (uint32_t)SZF*4u;
        uint32_t so = (uint32_t)(srow*PITCH + skq)*4u;
        #pragma unroll
        for (int j = 0; j < 8; j++) {
            int k = k0 + skq + j;
            cpa4(ab    + so + 4u*j, Arow + k0 + j, k < K);
            cpa4(bbase + so + 4u*j, Wrow + k0 + j, k < K);
        }
        asm volatile("cp.async.commit_group;" ::: "memory");
    };

    issue_tile(0, 0);
    int r = lane >> 2, c = lane & 3;

    for (int it = 0; it < NT; it++) {
        int buf = it & 1;
        if (it + 1 < NT) {
            issue_tile(it + 1, buf ^ 1);
            asm volatile("cp.async.wait_group 1;" ::: "memory");
        } else {
            asm volatile("cp.async.wait_group 0;" ::: "memory");
        }
        __syncthreads();
        const float* As = smf + buf*STAGEF;
        const float* Bs = As + SZF;
        #pragma unroll
        for (int ks = 0; ks < 4; ks++) {
            int kb = ks*8 + c;
            uint32_t ah[2][4], al[2][4], bh[4][2], bl[4][2];
            #pragma unroll
            for (int f = 0; f < 2; f++) {
                int mb = mw + f*16 + r;
                float x0 = As[mb*PITCH + kb];
                float x1 = As[(mb+8)*PITCH + kb];
                float x2 = As[mb*PITCH + kb + 4];
                float x3 = As[(mb+8)*PITCH + kb + 4];
                ah[f][0] = cvt_tf32(x0); al[f][0] = cvt_tf32(x0 - __uint_as_float(ah[f][0]));
                ah[f][1] = cvt_tf32(x1); al[f][1] = cvt_tf32(x1 - __uint_as_float(ah[f][1]));
                ah[f][2] = cvt_tf32(x2); al[f][2] = cvt_tf32(x2 - __uint_as_float(ah[f][2]));
                ah[f][3] = cvt_tf32(x3); al[f][3] = cvt_tf32(x3 - __uint_as_float(ah[f][3]));
            }
            #pragma unroll
            for (int g = 0; g < 4; g++) {
                int nb = nw + g*8 + r;
                float y0 = Bs[nb*PITCH + kb];
                float y1 = Bs[nb*PITCH + kb + 4];
                bh[g][0] = cvt_tf32(y0); bl[g][0] = cvt_tf32(y0 - __uint_as_float(bh[g][0]));
                bh[g][1] = cvt_tf32(y1); bl[g][1] = cvt_tf32(y1 - __uint_as_float(bh[g][1]));
            }
            #pragma unroll
            for (int f = 0; f < 2; f++)
                #pragma unroll
                for (int g = 0; g < 4; g++) {
                    mma_tf32(acc[f][g], ah[f], bh[g]);
                    mma_tf32(acc[f][g], al[f], bh[g]);
                    mma_tf32(acc[f][g], ah[f], bl[g]);
                }
        }
        __syncthreads();
    }

    // epilogue: frag (f,g): rows m0+mw+f*16+{r,r+8}, cols nw+g*8+2c+{0,1}
    #pragma unroll
    for (int g = 0; g < 4; g++) {
        int col = nw + g*8 + 2*c;
        float2 bv = *(const float2*)&bias[col];
        #pragma unroll
        for (int f = 0; f < 2; f++) {
            long row0 = m0 + mw + f*16 + r;
            float2 v0 = make_float2(acc[f][g][0] + bv.x, acc[f][g][1] + bv.y);
            float2 v1 = make_float2(acc[f][g][2] + bv.x, acc[f][g][3] + bv.y);
            *(float2*)&C[row0*HH + col]       = v0;
            *(float2*)&C[(row0 + 8)*HH + col] = v1;
        }
    }
}

// -------- gather + relu (GIN self-term + neighbor sum + ReLU) --------
__global__ void __launch_bounds__(256) gather_relu_kernel(
    const float* __restrict__ Y, float* __restrict__ Out)
{
    int wid  = threadIdx.x >> 5, lane = threadIdx.x & 31;
    int dst  = blockIdx.x * 8 + wid;
    int t    = blockIdx.y;
    if (dst >= NN) return;
    const float* base = Y + t * NN * HH;
    float4 acc = *(const float4*)&base[dst * HH + lane * 4];
    int s   = g_start[t*NN + dst];
    int cnt = g_cnt  [t*NN + dst];
    const int* ep = g_eidx + t*EE + s;
    int i = 0;
    for (; i + 4 <= cnt; i += 4) {
        int s0 = ep[i], s1 = ep[i+1], s2 = ep[i+2], s3 = ep[i+3];
        float4 v0 = *(const float4*)&base[s0*HH + lane*4];
        float4 v1 = *(const float4*)&base[s1*HH + lane*4];
        float4 v2 = *(const float4*)&base[s2*HH + lane*4];
        float4 v3 = *(const float4*)&base[s3*HH + lane*4];
        acc.x += v0.x + v1.x + v2.x + v3.x;
        acc.y += v0.y + v1.y + v2.y + v3.y;
        acc.z += v0.z + v1.z + v2.z + v3.z;
        acc.w += v0.w + v1.w + v2.w + v3.w;
    }
    for (; i < cnt; i++) {
        int s0 = ep[i];
        float4 v = *(const float4*)&base[s0*HH + lane*4];
        acc.x += v.x; acc.y += v.y; acc.z += v.z; acc.w += v.w;
    }
    acc.x = fmaxf(acc.x, 0.f); acc.y = fmaxf(acc.y, 0.f);
    acc.z = fmaxf(acc.z, 0.f); acc.w = fmaxf(acc.w, 0.f);
    *(float4*)&Out[(t*NN + dst)*HH + lane*4] = acc;
}

// ---------------- mean pool over N ----------------
__global__ void pool_kernel(const float* __restrict__ Hin) {
    int t = blockIdx.x, c = threadIdx.x;   // 128 threads
    const float* p = Hin + t*NN*HH + c;
    float s0 = 0, s1 = 0, s2 = 0, s3 = 0;
    for (int n = 0; n < NN; n += 4) {
        s0 += p[(n+0)*HH];
        s1 += p[(n+1)*HH];
        s2 += p[(n+2)*HH];
        s3 += p[(n+3)*HH];
    }
    g_pool[t*HH + c] = (s0 + s1 + s2 + s3) * (1.f / NN);
}

// -------- input-side LSTM gates --------
__global__ void __launch_bounds__(512) gx_kernel(
    const int* __restrict__ dok, const float* __restrict__ emb,
    const float* __restrict__ w_ih, const float* __restrict__ b_ih,
    const float* __restrict__ b_hh)
{
    __shared__ float sseq[HH + DD];
    int t = blockIdx.x, j = threadIdx.x;
    if (j < HH)            sseq[j] = g_pool[t*HH + j];
    else if (j < HH + DD)  sseq[j] = emb[dok[t]*DD + (j - HH)];
    __syncthreads();
    const float* wr = w_ih + j * (HH + DD);
    float a0 = b_ih[j] + b_hh[j], a1 = 0.f;
    #pragma unroll
    for (int k = 0; k < HH + DD; k += 2) {
        a0 += wr[k]   * sseq[k];
        a1 += wr[k+1] * sseq[k+1];
    }
    g_Gx[t*G4 + j] = a0 + a1;
}

// ---------------- sequential LSTM + final FC ----------------
#define SPITCH 68
__global__ void __launch_bounds__(512) lstm_kernel(
    const float* __restrict__ w_hh, const float* __restrict__ w_fc,
    const float* __restrict__ b_fc, float* __restrict__ out)
{
    extern __shared__ float sm[];
    float* sW   = sm;                  // 512*68
    float* sh   = sW + G4*SPITCH;      // 128
    float* sg   = sh + HH;             // 512
    float* sred = sg + G4;             // 32

    int tid = threadIdx.x;

    float4 rw[16];
    const float4* wg4 = (const float4*)(w_hh + tid * HH);
    #pragma unroll
    for (int i = 0; i < 16; i++) rw[i] = wg4[i];          // cols 0..63

    for (int i = tid; i < G4 * 64; i += 512) {            // cols 64..127
        int r = i >> 6, c = i & 63;
        sW[r*SPITCH + c] = w_hh[r*HH + 64 + c];
    }
    if (tid < HH) sh[tid] = 0.f;
    float c_state = 0.f;
    float wfc = (tid < HH) ? w_fc[tid] : 0.f;
    float bfc = b_fc[0];
    __syncthreads();

    const float4* wr4 = (const float4*)(sW + tid * SPITCH);

    for (int t = 0; t < TT; t++) {
        const float4* sh4 = (const float4*)sh;
        float a0 = 0, a1 = 0, a2 = 0, a3 = 0;
        #pragma unroll
        for (int k = 0; k < 16; k++) {
            float4 hv = sh4[k]; float4 w = rw[k];
            a0 += w.x*hv.x; a1 += w.y*hv.y; a2 += w.z*hv.z; a3 += w.w*hv.w;
        }
        #pragma unroll
        for (int k = 0; k < 16; k++) {
            float4 hv = sh4[16 + k]; float4 w = wr4[k];
            a0 += w.x*hv.x; a1 += w.y*hv.y; a2 += w.z*hv.z; a3 += w.w*hv.w;
        }
        sg[tid] = g_Gx[t*G4 + tid] + (a0 + a1) + (a2 + a3);
        __syncthreads();
        if (tid < HH) {
            float ig = 1.f / (1.f + expf(-sg[tid]));
            float fg = 1.f / (1.f + expf(-sg[tid + HH]));
            float gg = tanhf(sg[tid + 2*HH]);
            float og = 1.f / (1.f + expf(-sg[tid + 3*HH]));
            c_state = fg * c_state + ig * gg;
            float h = og * tanhf(c_state);
            sh[tid] = h;
            float p = h * wfc;
            #pragma unroll
            for (int o = 16; o > 0; o >>= 1) p += __shfl_down_sync(0xffffffffu, p, o);
            if ((tid & 31) == 0) sred[tid >> 5] = p;
        }
        __syncthreads();
        if (tid == 0) out[t] = sred[0] + sred[1] + sred[2] + sred[3] + bfc;
    }
}

// ---------------- launch ----------------
extern "C" void kernel_launch(void* const* d_in, const int* in_sizes, int n_in,
                              void* d_out, int out_size)
{
    const float* x    = (const float*)d_in[0];
    const int*   ei   = (const int*)  d_in[1];
    const int*   dok  = (const int*)  d_in[2];
    const float* w1   = (const float*)d_in[3];
    const float* b1   = (const float*)d_in[4];
    const float* w2   = (const float*)d_in[5];
    const float* b2   = (const float*)d_in[6];
    const float* emb  = (const float*)d_in[7];
    const float* w_ih = (const float*)d_in[8];
    const float* w_hh = (const float*)d_in[9];
    const float* b_ih = (const float*)d_in[10];
    const float* b_hh = (const float*)d_in[11];
    const float* w_fc = (const float*)d_in[12];
    const float* b_fc = (const float*)d_in[13];
    float* out = (float*)d_out;

    float *pY, *pH1;
    cudaGetSymbolAddress((void**)&pY,  g_Y);
    cudaGetSymbolAddress((void**)&pH1, g_H1);

    // fused CSR build (shared by both GIN layers)
    csr_kernel<<<TT, 1024>>>(ei);

    size_t gsm = (size_t)(2*STAGEF) * sizeof(float);   // 73728 B
    cudaFuncSetAttribute(gemm_mma_kernel, cudaFuncAttributeMaxDynamicSharedMemorySize, (int)gsm);

    // GIN layer 1: y = x@w1^T + b1 ; h1 = relu(y[dst] + sum y[src])
    gemm_mma_kernel<<<TT*NN/BM, 512, gsm>>>(x, w1, b1, pY, FF);
    dim3 gg((NN + 7)/8, TT);
    gather_relu_kernel<<<gg, 256>>>(pY, pH1);

    // GIN layer 2
    gemm_mma_kernel<<<TT*NN/BM, 512, gsm>>>(pH1, w2, b2, pY, HH);
    gather_relu_kernel<<<gg, 256>>>(pY, pH1);

    // pool, LSTM input gates, sequential LSTM + FC
    pool_kernel<<<TT, HH>>>(pH1);
    gx_kernel<<<TT, 512>>>(dok, emb, w_ih, b_ih, b_hh);

    size_t lsm = (size_t)(G4*SPITCH + HH + G4 + 32) * sizeof(float);
    cudaFuncSetAttribute(lstm_kernel, cudaFuncAttributeMaxDynamicSharedMemorySize, (int)lsm);
    lstm_kernel<<<1, 512, lsm>>>(w_hh, w_fc, b_fc, out);
}

// round 8
// speedup vs baseline: 1.3390x; 1.2557x over previous
#include <cuda_runtime.h>
#include <math.h>
#include <stdint.h>

#define TT 128
#define NN 1000
#define EE 16000
#define FF 397
#define HH 128
#define DD 8
#define G4 512   // 4*HH
#define BM 128
#define BKT 32   // K per tile
#define PB2 20   // smem pitch in u32 (bf16 pairs): bank = (4r+c)%32, conflict-free

// ---- static scratch (allocation-free rule: __device__ globals) ----
__device__ float g_Y [TT*NN*HH];
__device__ float g_H1[TT*NN*HH];
__device__ int   g_cnt  [TT*NN];
__device__ int   g_start[TT*NN];
__device__ int   g_eidx [TT*EE];
__device__ float g_pool [TT*HH];
__device__ float g_Gx   [TT*G4];

// ---- helpers ----
__device__ __forceinline__ uint32_t bf16x2_pack(float lo, float hi) {
    uint32_t r;
    asm("cvt.rn.bf16x2.f32 %0, %1, %2;" : "=r"(r) : "f"(hi), "f"(lo));
    return r;
}
// bf16 -> f32 is exact: bits << 16
__device__ __forceinline__ float bf_lo_f(uint32_t p) { return __uint_as_float(p << 16); }
__device__ __forceinline__ float bf_hi_f(uint32_t p) { return __uint_as_float(p & 0xFFFF0000u); }

__device__ __forceinline__ void mma_bf16(float* d, const uint32_t* a, const uint32_t* b) {
    asm volatile("mma.sync.aligned.m16n8k16.row.col.f32.bf16.bf16.f32 "
                 "{%0,%1,%2,%3}, {%4,%5,%6,%7}, {%8,%9}, {%0,%1,%2,%3};"
                 : "+f"(d[0]), "+f"(d[1]), "+f"(d[2]), "+f"(d[3])
                 : "r"(a[0]), "r"(a[1]), "r"(a[2]), "r"(a[3]),
                   "r"(b[0]), "r"(b[1]));
}

// ---------------- fused CSR build: one block per timestep ----------------
__global__ void __launch_bounds__(1024) csr_kernel(const int* __restrict__ ei) {
    __shared__ int scnt[1024];
    __shared__ int sscan[1024];
    int t = blockIdx.x, tid = threadIdx.x;
    scnt[tid] = 0;
    __syncthreads();
    const int* srcp = ei + t*2*EE;
    const int* dstp = srcp + EE;
    for (int e = tid; e < EE; e += 1024) atomicAdd(&scnt[dstp[e]], 1);
    __syncthreads();
    int v = scnt[tid];
    sscan[tid] = v;
    __syncthreads();
    for (int off = 1; off < 1024; off <<= 1) {
        int u = (tid >= off) ? sscan[tid - off] : 0;
        __syncthreads();
        sscan[tid] += u;
        __syncthreads();
    }
    int start = sscan[tid] - v;
    if (tid < NN) { g_start[t*NN + tid] = start; g_cnt[t*NN + tid] = v; }
    __syncthreads();
    scnt[tid] = start;          // reuse as cursor
    __syncthreads();
    int* eix = g_eidx + t*EE;
    for (int e = tid; e < EE; e += 1024) {
        int d = dstp[e], s = srcp[e];
        int pos = atomicAdd(&scnt[d], 1);
        eix[pos] = s;
    }
}

// ==== tensor GEMM: C[M x 128] = A[M x K] @ W^T + bias (3xBF16 mma.sync) ====
// 512 thr = 16 warps (4m x 4n), warp tile 32x32, BK=32 (2 k16 steps).
// Producer threads split fp32 -> (bf16 hi, bf16 lo) ONCE per tile into
// pre-split smem (pitch 20 u32, conflict-free). Raw LDG prefetch of tile
// i+1 is issued before the compute block (latency hidden under 48 mmas).
__global__ void __launch_bounds__(512, 1) gemm_mma_kernel(
    const float* __restrict__ A, const float* __restrict__ W,
    const float* __restrict__ bias, float* __restrict__ C, int K)
{
    __shared__ uint32_t sAh[128*PB2], sAl[128*PB2];
    __shared__ uint32_t sBh[128*PB2], sBl[128*PB2];

    int tid = threadIdx.x;
    int lane = tid & 31, wid = tid >> 5;
    long m0 = (long)blockIdx.x * BM;

    int mw = (wid & 3) * 32;      // warp m offset
    int nw = (wid >> 2) * 32;     // warp n offset
    int r = lane >> 2, c = lane & 3;

    float acc[2][4][4];
    #pragma unroll
    for (int f = 0; f < 2; f++)
        #pragma unroll
        for (int g = 0; g < 4; g++)
            #pragma unroll
            for (int e = 0; e < 4; e++) acc[f][g][e] = 0.f;

    // staging: thread owns 8 consecutive k of one row (A and B)
    int srow = tid >> 2, skq = (tid & 3) * 8;
    const float* Arow = A + (m0 + srow) * (long)K;
    const float* Wrow = W + (long)srow * K;

    int NT = (K + BKT - 1) / BKT;
    float rA[8], rB[8];

    // prefetch tile 0
    #pragma unroll
    for (int j = 0; j < 8; j++) {
        int k = skq + j;
        rA[j] = (k < K) ? Arow[k] : 0.f;
        rB[j] = (k < K) ? Wrow[k] : 0.f;
    }

    for (int it = 0; it < NT; it++) {
        __syncthreads();   // consumers of previous tile done
        // split + store (4 x STS.128 per thread)
        uint32_t ha[4], la[4], hb[4], lb[4];
        #pragma unroll
        for (int j = 0; j < 4; j++) {
            float x0 = rA[2*j], x1 = rA[2*j+1];
            uint32_t h = bf16x2_pack(x0, x1);
            ha[j] = h;
            la[j] = bf16x2_pack(x0 - bf_lo_f(h), x1 - bf_hi_f(h));
            float y0 = rB[2*j], y1 = rB[2*j+1];
            uint32_t hbp = bf16x2_pack(y0, y1);
            hb[j] = hbp;
            lb[j] = bf16x2_pack(y0 - bf_lo_f(hbp), y1 - bf_hi_f(hbp));
        }
        int so = srow*PB2 + (skq >> 1);
        *(uint4*)&sAh[so] = *(uint4*)ha;
        *(uint4*)&sAl[so] = *(uint4*)la;
        *(uint4*)&sBh[so] = *(uint4*)hb;
        *(uint4*)&sBl[so] = *(uint4*)lb;
        __syncthreads();
        // issue raw prefetch of next tile (overlaps the mma block)
        if (it + 1 < NT) {
            int k0 = (it + 1) * BKT;
            #pragma unroll
            for (int j = 0; j < 8; j++) {
                int k = k0 + skq + j;
                rA[j] = (k < K) ? Arow[k] : 0.f;
                rB[j] = (k < K) ? Wrow[k] : 0.f;
            }
        }
        // compute: 2 k16 steps x 8 frag products x 3 terms
        #pragma unroll
        for (int ks = 0; ks < 2; ks++) {
            int kp = ks * 8;
            uint32_t ah[2][4], al[2][4], bh[4][2], bl[4][2];
            #pragma unroll
            for (int f = 0; f < 2; f++) {
                int mb = (mw + f*16 + r) * PB2 + kp + c;
                int mb8 = mb + 8*PB2;
                ah[f][0] = sAh[mb];     ah[f][1] = sAh[mb8];
                ah[f][2] = sAh[mb + 4]; ah[f][3] = sAh[mb8 + 4];
                al[f][0] = sAl[mb];     al[f][1] = sAl[mb8];
                al[f][2] = sAl[mb + 4]; al[f][3] = sAl[mb8 + 4];
            }
            #pragma unroll
            for (int g = 0; g < 4; g++) {
                int nb = (nw + g*8 + r) * PB2 + kp + c;
                bh[g][0] = sBh[nb]; bh[g][1] = sBh[nb + 4];
                bl[g][0] = sBl[nb]; bl[g][1] = sBl[nb + 4];
            }
            #pragma unroll
            for (int f = 0; f < 2; f++)
                #pragma unroll
                for (int g = 0; g < 4; g++) {
                    mma_bf16(acc[f][g], ah[f], bh[g]);
                    mma_bf16(acc[f][g], al[f], bh[g]);
                    mma_bf16(acc[f][g], ah[f], bl[g]);
                }
        }
    }

    // epilogue: frag (f,g): rows m0+mw+f*16+{r,r+8}, cols nw+g*8+2c+{0,1}
    #pragma unroll
    for (int g = 0; g < 4; g++) {
        int col = nw + g*8 + 2*c;
        float2 bv = *(const float2*)&bias[col];
        #pragma unroll
        for (int f = 0; f < 2; f++) {
            long row0 = m0 + mw + f*16 + r;
            float2 v0 = make_float2(acc[f][g][0] + bv.x, acc[f][g][1] + bv.y);
            float2 v1 = make_float2(acc[f][g][2] + bv.x, acc[f][g][3] + bv.y);
            *(float2*)&C[row0*HH + col]       = v0;
            *(float2*)&C[(row0 + 8)*HH + col] = v1;
        }
    }
}

// -------- gather + relu (GIN self-term + neighbor sum + ReLU) --------
__global__ void __launch_bounds__(256) gather_relu_kernel(
    const float* __restrict__ Y, float* __restrict__ Out)
{
    int wid  = threadIdx.x >> 5, lane = threadIdx.x & 31;
    int dst  = blockIdx.x * 8 + wid;
    int t    = blockIdx.y;
    if (dst >= NN) return;
    const float* base = Y + t * NN * HH;
    float4 acc = *(const float4*)&base[dst * HH + lane * 4];
    int s   = g_start[t*NN + dst];
    int cnt = g_cnt  [t*NN + dst];
    const int* ep = g_eidx + t*EE + s;
    int i = 0;
    for (; i + 4 <= cnt; i += 4) {
        int s0 = ep[i], s1 = ep[i+1], s2 = ep[i+2], s3 = ep[i+3];
        float4 v0 = *(const float4*)&base[s0*HH + lane*4];
        float4 v1 = *(const float4*)&base[s1*HH + lane*4];
        float4 v2 = *(const float4*)&base[s2*HH + lane*4];
        float4 v3 = *(const float4*)&base[s3*HH + lane*4];
        acc.x += v0.x + v1.x + v2.x + v3.x;
        acc.y += v0.y + v1.y + v2.y + v3.y;
        acc.z += v0.z + v1.z + v2.z + v3.z;
        acc.w += v0.w + v1.w + v2.w + v3.w;
    }
    for (; i < cnt; i++) {
        int s0 = ep[i];
        float4 v = *(const float4*)&base[s0*HH + lane*4];
        acc.x += v.x; acc.y += v.y; acc.z += v.z; acc.w += v.w;
    }
    acc.x = fmaxf(acc.x, 0.f); acc.y = fmaxf(acc.y, 0.f);
    acc.z = fmaxf(acc.z, 0.f); acc.w = fmaxf(acc.w, 0.f);
    *(float4*)&Out[(t*NN + dst)*HH + lane*4] = acc;
}

// ---------------- mean pool over N ----------------
__global__ void pool_kernel(const float* __restrict__ Hin) {
    int t = blockIdx.x, c = threadIdx.x;   // 128 threads
    const float* p = Hin + t*NN*HH + c;
    float s0 = 0, s1 = 0, s2 = 0, s3 = 0;
    for (int n = 0; n < NN; n += 4) {
        s0 += p[(n+0)*HH];
        s1 += p[(n+1)*HH];
        s2 += p[(n+2)*HH];
        s3 += p[(n+3)*HH];
    }
    g_pool[t*HH + c] = (s0 + s1 + s2 + s3) * (1.f / NN);
}

// -------- input-side LSTM gates --------
__global__ void __launch_bounds__(512) gx_kernel(
    const int* __restrict__ dok, const float* __restrict__ emb,
    const float* __restrict__ w_ih, const float* __restrict__ b_ih,
    const float* __restrict__ b_hh)
{
    __shared__ float sseq[HH + DD];
    int t = blockIdx.x, j = threadIdx.x;
    if (j < HH)            sseq[j] = g_pool[t*HH + j];
    else if (j < HH + DD)  sseq[j] = emb[dok[t]*DD + (j - HH)];
    __syncthreads();
    const float* wr = w_ih + j * (HH + DD);
    float a0 = b_ih[j] + b_hh[j], a1 = 0.f;
    #pragma unroll
    for (int k = 0; k < HH + DD; k += 2) {
        a0 += wr[k]   * sseq[k];
        a1 += wr[k+1] * sseq[k+1];
    }
    g_Gx[t*G4 + j] = a0 + a1;
}

// ---------------- sequential LSTM + final FC ----------------
#define SPITCH 68
__global__ void __launch_bounds__(512) lstm_kernel(
    const float* __restrict__ w_hh, const float* __restrict__ w_fc,
    const float* __restrict__ b_fc, float* __restrict__ out)
{
    extern __shared__ float sm[];
    float* sW   = sm;                  // 512*68
    float* sh   = sW + G4*SPITCH;      // 128
    float* sg   = sh + HH;             // 512
    float* sred = sg + G4;             // 32

    int tid = threadIdx.x;

    float4 rw[16];
    const float4* wg4 = (const float4*)(w_hh + tid * HH);
    #pragma unroll
    for (int i = 0; i < 16; i++) rw[i] = wg4[i];          // cols 0..63

    for (int i = tid; i < G4 * 64; i += 512) {            // cols 64..127
        int r = i >> 6, c = i & 63;
        sW[r*SPITCH + c] = w_hh[r*HH + 64 + c];
    }
    if (tid < HH) sh[tid] = 0.f;
    float c_state = 0.f;
    float wfc = (tid < HH) ? w_fc[tid] : 0.f;
    float bfc = b_fc[0];
    __syncthreads();

    const float4* wr4 = (const float4*)(sW + tid * SPITCH);

    for (int t = 0; t < TT; t++) {
        const float4* sh4 = (const float4*)sh;
        float a0 = 0, a1 = 0, a2 = 0, a3 = 0;
        #pragma unroll
        for (int k = 0; k < 16; k++) {
            float4 hv = sh4[k]; float4 w = rw[k];
            a0 += w.x*hv.x; a1 += w.y*hv.y; a2 += w.z*hv.z; a3 += w.w*hv.w;
        }
        #pragma unroll
        for (int k = 0; k < 16; k++) {
            float4 hv = sh4[16 + k]; float4 w = wr4[k];
            a0 += w.x*hv.x; a1 += w.y*hv.y; a2 += w.z*hv.z; a3 += w.w*hv.w;
        }
        sg[tid] = g_Gx[t*G4 + tid] + (a0 + a1) + (a2 + a3);
        __syncthreads();
        if (tid < HH) {
            float ig = 1.f / (1.f + expf(-sg[tid]));
            float fg = 1.f / (1.f + expf(-sg[tid + HH]));
            float gg = tanhf(sg[tid + 2*HH]);
            float og = 1.f / (1.f + expf(-sg[tid + 3*HH]));
            c_state = fg * c_state + ig * gg;
            float h = og * tanhf(c_state);
            sh[tid] = h;
            float p = h * wfc;
            #pragma unroll
            for (int o = 16; o > 0; o >>= 1) p += __shfl_down_sync(0xffffffffu, p, o);
            if ((tid & 31) == 0) sred[tid >> 5] = p;
        }
        __syncthreads();
        if (tid == 0) out[t] = sred[0] + sred[1] + sred[2] + sred[3] + bfc;
    }
}

// ---------------- launch ----------------
extern "C" void kernel_launch(void* const* d_in, const int* in_sizes, int n_in,
                              void* d_out, int out_size)
{
    const float* x    = (const float*)d_in[0];
    const int*   ei   = (const int*)  d_in[1];
    const int*   dok  = (const int*)  d_in[2];
    const float* w1   = (const float*)d_in[3];
    const float* b1   = (const float*)d_in[4];
    const float* w2   = (const float*)d_in[5];
    const float* b2   = (const float*)d_in[6];
    const float* emb  = (const float*)d_in[7];
    const float* w_ih = (const float*)d_in[8];
    const float* w_hh = (const float*)d_in[9];
    const float* b_ih = (const float*)d_in[10];
    const float* b_hh = (const float*)d_in[11];
    const float* w_fc = (const float*)d_in[12];
    const float* b_fc = (const float*)d_in[13];
    float* out = (float*)d_out;

    float *pY, *pH1;
    cudaGetSymbolAddress((void**)&pY,  g_Y);
    cudaGetSymbolAddress((void**)&pH1, g_H1);

    // fused CSR build (shared by both GIN layers)
    csr_kernel<<<TT, 1024>>>(ei);

    // GIN layer 1: y = x@w1^T + b1 ; h1 = relu(y[dst] + sum y[src])
    gemm_mma_kernel<<<TT*NN/BM, 512>>>(x, w1, b1, pY, FF);
    dim3 gg((NN + 7)/8, TT);
    gather_relu_kernel<<<gg, 256>>>(pY, pH1);

    // GIN layer 2
    gemm_mma_kernel<<<TT*NN/BM, 512>>>(pH1, w2, b2, pY, HH);
    gather_relu_kernel<<<gg, 256>>>(pY, pH1);

    // pool, LSTM input gates, sequential LSTM + FC
    pool_kernel<<<TT, HH>>>(pH1);
    gx_kernel<<<TT, 512>>>(dok, emb, w_ih, b_ih, b_hh);

    size_t lsm = (size_t)(G4*SPITCH + HH + G4 + 32) * sizeof(float);
    cudaFuncSetAttribute(lstm_kernel, cudaFuncAttributeMaxDynamicSharedMemorySize, (int)lsm);
    lstm_kernel<<<1, 512, lsm>>>(w_hh, w_fc, b_fc, out);
}